// round 15
// baseline (speedup 1.0000x reference)
#include <cuda_runtime.h>
#include <cuda_fp16.h>
#include <cstdint>

// ===========================================================================
// Scratch (__device__ globals; no allocation allowed)
// Split format: uint2 { hi_half2, lo_half2 } covering 2 consecutive channels,
// value v stored as hi+lo = 256*v (fp16 pair), consumed by fp16x2 MMA scheme.
// ===========================================================================
__device__ uint2 g_a1s[32u * 128u * 128u * 64u / 2];   // conv1 out split NHWC
__device__ uint2 g_a2s[32u * 64u * 64u * 128u / 2];
__device__ uint2 g_a3s[32u * 32u * 32u * 256u / 2];
__device__ uint2 g_zfs[8192u * 256u / 2];              // conv4 out split == zf
__device__ uint2 g_wt1s[64u * 48u / 2];                // w1 split [co][ci*16+tap]
__device__ uint2 g_wt2s[128u * 1024u / 2];             // weights split [co][tap*CI+ci]
__device__ uint2 g_wt3s[256u * 2048u / 2];
__device__ uint2 g_wt4s[256u * 4096u / 2];
__device__ uint2 g_cbs[8192u * 256u / 2];              // codebook split
__device__ float g_cbnorm[8192];
__device__ unsigned long long g_min[8192];

// ===========================================================================
// Split helpers (epilogue/pre-pass only; GEMM mainloops have zero ALU)
// ===========================================================================
__device__ __forceinline__ uint32_t packh2(__half x, __half y) {
    __half2 h = __halves2half2(x, y);
    return *reinterpret_cast<uint32_t*>(&h);
}
__device__ __forceinline__ uint2 splitpk(float x, float y) {
    float sx = x * 256.f, sy = y * 256.f;
    __half hx = __float2half_rn(sx), hy = __float2half_rn(sy);
    float rx = sx - __half2float(hx), ry = sy - __half2float(hy);
    uint2 r;
    r.x = packh2(hx, hy);
    r.y = packh2(__float2half_rn(rx), __float2half_rn(ry));
    return r;
}

__device__ __forceinline__ void mma16(float* d, const uint32_t* a, const uint32_t* b) {
    asm volatile(
        "mma.sync.aligned.m16n8k16.row.col.f32.f16.f16.f32 "
        "{%0,%1,%2,%3}, {%4,%5,%6,%7}, {%8,%9}, {%0,%1,%2,%3};"
        : "+f"(d[0]), "+f"(d[1]), "+f"(d[2]), "+f"(d[3])
        : "r"(a[0]), "r"(a[1]), "r"(a[2]), "r"(a[3]), "r"(b[0]), "r"(b[1]));
}

// SMEM buffer (u32 units): AH[2048] AL[2048] BH[2048] BL[2048] = 8192 u32 = 32KB.
static constexpr int BUF_U32 = 8192;
static constexpr int GEMM_SMEM = 128 * 4 + 2 * BUF_U32 * 4;   // 66048 bytes

// Compute one K=32 chunk. Warp tile 64x32 (4 m-blocks x 4 n-blocks), 8 warps 2x4.
__device__ __forceinline__ void compute_chunk(const uint32_t* buf, int wm, int wn, int lane,
                                              float acc[4][4][4]) {
    const uint32_t* AH = buf;
    const uint32_t* AL = buf + 2048;
    const uint32_t* BH = buf + 4096;
    const uint32_t* BL = buf + 6144;
#pragma unroll
    for (int s = 0; s < 2; s++) {
        uint4 ah[4], al[4];
        uint2 bh[4], bl[4];
#pragma unroll
        for (int i = 0; i < 4; i++) {
            int idx = ((s * 8 + wm * 4 + i) * 32 + lane) * 4;
            ah[i] = *reinterpret_cast<const uint4*>(AH + idx);
            al[i] = *reinterpret_cast<const uint4*>(AL + idx);
        }
#pragma unroll
        for (int j = 0; j < 4; j++) {
            int idx = ((s * 16 + wn * 4 + j) * 32 + lane) * 2;
            bh[j] = *reinterpret_cast<const uint2*>(BH + idx);
            bl[j] = *reinterpret_cast<const uint2*>(BL + idx);
        }
#pragma unroll
        for (int i = 0; i < 4; i++)
#pragma unroll
            for (int j = 0; j < 4; j++) {
                mma16(acc[i][j], &ah[i].x, &bh[j].x);
                mma16(acc[i][j], &al[i].x, &bh[j].x);
                mma16(acc[i][j], &ah[i].x, &bl[j].x);
            }
    }
}

// Fill stores: pa0/pa1 = rows g,g+8, [s*2+p] uint2 pairs; pure register packing.
__device__ __forceinline__ void stsA_pk(uint32_t* base, int mblk, int lane,
                                        const uint2* pa0, const uint2* pa1) {
#pragma unroll
    for (int s = 0; s < 2; s++) {
        uint4 h = make_uint4(pa0[s * 2 + 0].x, pa1[s * 2 + 0].x, pa0[s * 2 + 1].x, pa1[s * 2 + 1].x);
        uint4 l = make_uint4(pa0[s * 2 + 0].y, pa1[s * 2 + 0].y, pa0[s * 2 + 1].y, pa1[s * 2 + 1].y);
        int idx = ((s * 8 + mblk) * 32 + lane) * 4;
        *reinterpret_cast<uint4*>(base + idx) = h;
        *reinterpret_cast<uint4*>(base + 2048 + idx) = l;
    }
}
__device__ __forceinline__ void stsB_pk(uint32_t* base, int nblk, int lane, const uint2* pb) {
#pragma unroll
    for (int s = 0; s < 2; s++) {
        uint2 h = make_uint2(pb[s * 2 + 0].x, pb[s * 2 + 1].x);
        uint2 l = make_uint2(pb[s * 2 + 0].y, pb[s * 2 + 1].y);
        int idx = ((s * 16 + nblk) * 32 + lane) * 2;
        *reinterpret_cast<uint2*>(base + 4096 + idx) = h;
        *reinterpret_cast<uint2*>(base + 6144 + idx) = l;
    }
}

// ===========================================================================
// Weight transpose + split (conv2-4): w[co][ci][kh][kw] -> wTs[co][tap*CI+ci]
// ===========================================================================
__global__ void wtrans_kernel(const float* __restrict__ w, uint2* __restrict__ wTs,
                              int CI, int CO) {
    int id = blockIdx.x * 256 + threadIdx.x;
    int K = CI * 16;
    if (id >= CO * K / 2) return;
    int co = id / (K / 2);
    int r2 = id % (K / 2);
    int k0 = 2 * r2, k1 = k0 + 1;
    int tap0 = k0 / CI, ci0 = k0 % CI;
    int tap1 = k1 / CI, ci1 = k1 % CI;
    float v0 = w[(co * CI + ci0) * 16 + tap0];
    float v1 = w[(co * CI + ci1) * 16 + tap1];
    wTs[id] = splitpk(v0, v1);
}

// conv1 weights: w1[co][ci][tap] -> wt1s[co][k=ci*16+tap] (ci-major, K=48)
__global__ void wtrans1_kernel(const float* __restrict__ w, uint2* __restrict__ wTs) {
    int id = blockIdx.x * 256 + threadIdx.x;
    if (id >= 64 * 24) return;
    int co = id / 24;
    int r2 = id % 24;
    int k0 = 2 * r2;                    // k = ci*16 + tap, contiguous
    float v0 = w[co * 48 + k0];
    float v1 = w[co * 48 + k0 + 1];
    wTs[id] = splitpk(v0, v1);
}

// ===========================================================================
// Conv1 tensorized: M=128 pixels x N=64 cout, K=48 (s=ci). NCHW in -> split NHWC.
// One-shot K (3 k16-steps), 8 warps 4m x 2n, warp tile 32x32.
// ===========================================================================
__global__ __launch_bounds__(256) void conv1_mma(const float* __restrict__ x,
                                                 const uint2* __restrict__ wt1s,
                                                 const float* __restrict__ bias,
                                                 uint2* __restrict__ outs) {
    __shared__ float aux[64];
    __shared__ __align__(16) uint32_t sbuf[9216];   // AH 3072 | AL 3072 | BH 1536 | BL 1536
    uint32_t* AH = sbuf;
    uint32_t* AL = sbuf + 3072;
    uint32_t* BH = sbuf + 6144;
    uint32_t* BL = sbuf + 7680;

    int tid = threadIdx.x, lane = tid & 31, wid = tid >> 5;
    int g = lane >> 2, t = lane & 3;
    int rowBase = blockIdx.x * 128;
    if (tid < 64) aux[tid] = bias[tid];

    // --- A fill: warp wid = m-block; rows r0=base+wid*16+g, r1=r0+8 ---
    int r0 = rowBase + wid * 16 + g;
    int r1 = r0 + 8;
    int n0 = r0 >> 14, rp0 = r0 & 16383;
    int n1 = r1 >> 14, rp1 = r1 & 16383;
    int hb0 = 2 * (rp0 >> 7) - 1, wb0 = 2 * (rp0 & 127) - 1;
    int hb1 = 2 * (rp1 >> 7) - 1, wb1 = 2 * (rp1 & 127) - 1;

    uint2 pa0[6], pa1[6];   // [ci*2 + p], pair of taps (2t+8p, 2t+8p+1)
#pragma unroll
    for (int ci = 0; ci < 3; ci++) {
        const float* xc0 = x + (((size_t)n0 * 3 + ci) << 16);
        const float* xc1 = x + (((size_t)n1 * 3 + ci) << 16);
#pragma unroll
        for (int p = 0; p < 2; p++) {
            int tapA = 2 * t + 8 * p;
            int tapB = tapA + 1;
            int khA = tapA >> 2, kwA = tapA & 3;
            int khB = tapB >> 2, kwB = tapB & 3;
            int hA0 = hb0 + khA, wA0 = wb0 + kwA, hB0 = hb0 + khB, wB0 = wb0 + kwB;
            int hA1 = hb1 + khA, wA1 = wb1 + kwA, hB1 = hb1 + khB, wB1 = wb1 + kwB;
            float vA0 = ((unsigned)hA0 < 256u && (unsigned)wA0 < 256u) ? __ldg(xc0 + hA0 * 256 + wA0) : 0.f;
            float vB0 = ((unsigned)hB0 < 256u && (unsigned)wB0 < 256u) ? __ldg(xc0 + hB0 * 256 + wB0) : 0.f;
            float vA1 = ((unsigned)hA1 < 256u && (unsigned)wA1 < 256u) ? __ldg(xc1 + hA1 * 256 + wA1) : 0.f;
            float vB1 = ((unsigned)hB1 < 256u && (unsigned)wB1 < 256u) ? __ldg(xc1 + hB1 * 256 + wB1) : 0.f;
            pa0[ci * 2 + p] = splitpk(vA0, vB0);
            pa1[ci * 2 + p] = splitpk(vA1, vB1);
        }
    }
#pragma unroll
    for (int s = 0; s < 3; s++) {
        uint4 h = make_uint4(pa0[s * 2 + 0].x, pa1[s * 2 + 0].x, pa0[s * 2 + 1].x, pa1[s * 2 + 1].x);
        uint4 l = make_uint4(pa0[s * 2 + 0].y, pa1[s * 2 + 0].y, pa0[s * 2 + 1].y, pa1[s * 2 + 1].y);
        int idx = ((s * 8 + wid) * 32 + lane) * 4;
        *reinterpret_cast<uint4*>(AH + idx) = h;
        *reinterpret_cast<uint4*>(AL + idx) = l;
    }

    // --- B fill: warp wid = n-block; col = wid*8 + g; 24 uint2 per co row ---
    {
        size_t wr = (size_t)(wid * 8 + g) * 24;
#pragma unroll
        for (int s = 0; s < 3; s++) {
            uint2 u0 = __ldg(wt1s + wr + s * 8 + t);        // k = s*16 + 2t
            uint2 u1 = __ldg(wt1s + wr + s * 8 + t + 4);    // k = s*16 + 2t + 8
            int idx = ((s * 8 + wid) * 32 + lane) * 2;
            *reinterpret_cast<uint2*>(BH + idx) = make_uint2(u0.x, u1.x);
            *reinterpret_cast<uint2*>(BL + idx) = make_uint2(u0.y, u1.y);
        }
    }
    __syncthreads();

    // --- compute: warp 4m x 2n; warp tile 32 rows (2 mblk) x 32 cols (4 nblk) ---
    int wm = wid >> 1, wn = wid & 1;
    float acc[2][4][4];
#pragma unroll
    for (int i = 0; i < 2; i++)
#pragma unroll
        for (int j = 0; j < 4; j++)
#pragma unroll
            for (int e = 0; e < 4; e++) acc[i][j][e] = 0.f;

#pragma unroll
    for (int s = 0; s < 3; s++) {
        uint4 ah[2], al[2];
        uint2 bh[4], bl[4];
#pragma unroll
        for (int i = 0; i < 2; i++) {
            int idx = ((s * 8 + wm * 2 + i) * 32 + lane) * 4;
            ah[i] = *reinterpret_cast<const uint4*>(AH + idx);
            al[i] = *reinterpret_cast<const uint4*>(AL + idx);
        }
#pragma unroll
        for (int j = 0; j < 4; j++) {
            int idx = ((s * 8 + wn * 4 + j) * 32 + lane) * 2;
            bh[j] = *reinterpret_cast<const uint2*>(BH + idx);
            bl[j] = *reinterpret_cast<const uint2*>(BL + idx);
        }
#pragma unroll
        for (int i = 0; i < 2; i++)
#pragma unroll
            for (int j = 0; j < 4; j++) {
                mma16(acc[i][j], &ah[i].x, &bh[j].x);
                mma16(acc[i][j], &al[i].x, &bh[j].x);
                mma16(acc[i][j], &ah[i].x, &bl[j].x);
            }
    }

    // --- epilogue: descale + bias + relu, split NHWC store ---
    const float ds = 1.f / 65536.f;
#pragma unroll
    for (int i = 0; i < 2; i++) {
        int rlo = rowBase + (wm * 2 + i) * 16 + g;
        int rhi = rlo + 8;
#pragma unroll
        for (int j = 0; j < 4; j++) {
            int c = (wn * 4 + j) * 8 + 2 * t;
            float b0 = aux[c], b1 = aux[c + 1];
            outs[((size_t)rlo * 64 + c) >> 1] =
                splitpk(fmaxf(acc[i][j][0] * ds + b0, 0.f), fmaxf(acc[i][j][1] * ds + b1, 0.f));
            outs[((size_t)rhi * 64 + c) >> 1] =
                splitpk(fmaxf(acc[i][j][2] * ds + b0, 0.f), fmaxf(acc[i][j][3] * ds + b1, 0.f));
        }
    }
}

// ===========================================================================
// Tensor-core implicit-GEMM conv (k=4 s=2 p=1) + bias + ReLU.
// split NHWC in -> split NHWC out. Block 128x128, K=CI*16 by 32; 8 warps 64x32.
// Mainloop: LDG(uint2) -> STS -> LDS -> MMA. No ALU.
// ===========================================================================
template <int CI, int CO, int HI, int WI>
__global__ __launch_bounds__(256) void conv_mma(const uint2* __restrict__ in,
                                                const uint2* __restrict__ wTs,
                                                const float* __restrict__ bias,
                                                uint2* __restrict__ outs) {
    constexpr int HO = HI / 2, WO = WI / 2;
    constexpr int K = CI * 16;
    constexpr int NCH = K / 32;
    extern __shared__ __align__(16) float smem[];
    float* aux = smem;
    uint32_t* bufs = reinterpret_cast<uint32_t*>(smem + 128);

    int tid = threadIdx.x, lane = tid & 31, wid = tid >> 5;
    int wm = wid >> 2, wn = wid & 3;
    int g = lane >> 2, t = lane & 3;
    int rowBase = blockIdx.x * 128;
    int co0 = blockIdx.y * 128;

    if (tid < 128) aux[tid] = bias[co0 + tid];

    // --- A fill: warp wid = m-block; rows g and g+8 ---
    int rA0 = rowBase + wid * 16 + g;
    int rA1 = rA0 + 8;
    int n0 = rA0 / (HO * WO), rp0 = rA0 % (HO * WO);
    int n1 = rA1 / (HO * WO), rp1 = rA1 % (HO * WO);
    int hb0 = 2 * (rp0 / WO) - 1, wb0 = 2 * (rp0 % WO) - 1;
    int hb1 = 2 * (rp1 / WO) - 1, wb1 = 2 * (rp1 % WO) - 1;
    size_t ab0 = (size_t)n0 * HI * WI * CI;
    size_t ab1 = (size_t)n1 * HI * WI * CI;

    // --- B fill: warp wid covers n-blocks wid, wid+8; col = nblk*8 + g ---
    size_t wb0i = ((size_t)(co0 + wid * 8 + g) * K) >> 1;
    size_t wb1i = ((size_t)(co0 + (wid + 8) * 8 + g) * K) >> 1;

    uint2 pa0[4], pa1[4], pb0[4], pb1[4];
    auto loadA = [&](int kk) {
        int kk32 = kk * 32;
        int tap = kk32 / CI, ci0 = kk32 % CI;
        int kh = tap >> 2, kw = tap & 3;
        int hi0 = hb0 + kh, wi0 = wb0 + kw;
        int hi1 = hb1 + kh, wi1 = wb1 + kw;
        bool ok0 = (unsigned)hi0 < (unsigned)HI && (unsigned)wi0 < (unsigned)WI;
        bool ok1 = (unsigned)hi1 < (unsigned)HI && (unsigned)wi1 < (unsigned)WI;
        size_t b0 = (ab0 + ((size_t)hi0 * WI + wi0) * CI + ci0) >> 1;
        size_t b1 = (ab1 + ((size_t)hi1 * WI + wi1) * CI + ci0) >> 1;
        uint2 z = make_uint2(0u, 0u);
#pragma unroll
        for (int s = 0; s < 2; s++)
#pragma unroll
            for (int p = 0; p < 2; p++) {
                int off = s * 8 + t + 4 * p;
                pa0[s * 2 + p] = ok0 ? __ldg(in + b0 + off) : z;
                pa1[s * 2 + p] = ok1 ? __ldg(in + b1 + off) : z;
            }
    };
    auto loadB = [&](int kk) {
#pragma unroll
        for (int s = 0; s < 2; s++)
#pragma unroll
            for (int p = 0; p < 2; p++) {
                int off = kk * 16 + s * 8 + t + 4 * p;
                pb0[s * 2 + p] = __ldg(wTs + wb0i + off);
                pb1[s * 2 + p] = __ldg(wTs + wb1i + off);
            }
    };
    auto stsAB = [&](int buf) {
        uint32_t* base = bufs + buf * BUF_U32;
        stsA_pk(base, wid, lane, pa0, pa1);
        stsB_pk(base, wid, lane, pb0);
        stsB_pk(base, wid + 8, lane, pb1);
    };

    float acc[4][4][4];
#pragma unroll
    for (int i = 0; i < 4; i++)
#pragma unroll
        for (int j = 0; j < 4; j++)
#pragma unroll
            for (int e = 0; e < 4; e++) acc[i][j][e] = 0.f;

    loadA(0); loadB(0);
    stsAB(0);
    __syncthreads();

    for (int kk = 0; kk < NCH; kk++) {
        if (kk + 1 < NCH) { loadA(kk + 1); loadB(kk + 1); }
        compute_chunk(bufs + (kk & 1) * BUF_U32, wm, wn, lane, acc);
        if (kk + 1 < NCH) stsAB((kk + 1) & 1);
        __syncthreads();
    }

    // epilogue: descale + bias + relu, split store
    const float ds = 1.f / 65536.f;
#pragma unroll
    for (int i = 0; i < 4; i++) {
        int rlo = rowBase + (wm * 4 + i) * 16 + g;
        int rhi = rlo + 8;
#pragma unroll
        for (int j = 0; j < 4; j++) {
            int c = (wn * 4 + j) * 8 + 2 * t;
            float b0 = aux[c], b1 = aux[c + 1];
            outs[((size_t)rlo * CO + co0 + c) >> 1] =
                splitpk(fmaxf(acc[i][j][0] * ds + b0, 0.f), fmaxf(acc[i][j][1] * ds + b1, 0.f));
            outs[((size_t)rhi * CO + co0 + c) >> 1] =
                splitpk(fmaxf(acc[i][j][2] * ds + b0, 0.f), fmaxf(acc[i][j][3] * ds + b1, 0.f));
        }
    }
}

// ===========================================================================
// Tensor-core VQ: S = zf @ cb^T; d = ||c||^2 - 2S; row argmin. Split inputs.
// ===========================================================================
__global__ __launch_bounds__(256) void vq_mma(const uint2* __restrict__ zfs,
                                              const uint2* __restrict__ cbs) {
    constexpr int NCH = 8;   // K = 256
    extern __shared__ __align__(16) float smem[];
    float* aux = smem;
    uint32_t* bufs = reinterpret_cast<uint32_t*>(smem + 128);
    __shared__ unsigned long long smin[128];

    int tid = threadIdx.x, lane = tid & 31, wid = tid >> 5;
    int wm = wid >> 2, wn = wid & 3;
    int g = lane >> 2, t = lane & 3;
    int colBase = blockIdx.x * 128;
    int rowBase = blockIdx.y * 128;

    if (tid < 128) { aux[tid] = g_cbnorm[colBase + tid]; smin[tid] = ~0ULL; }

    size_t a0i = ((size_t)(rowBase + wid * 16 + g) * 256) >> 1;
    size_t a1i = a0i + 1024;    // +8 rows
    size_t b0i = ((size_t)(colBase + wid * 8 + g) * 256) >> 1;
    size_t b1i = ((size_t)(colBase + (wid + 8) * 8 + g) * 256) >> 1;

    uint2 pa0[4], pa1[4], pb0[4], pb1[4];
    auto loadAB = [&](int kk) {
#pragma unroll
        for (int s = 0; s < 2; s++)
#pragma unroll
            for (int p = 0; p < 2; p++) {
                int off = kk * 16 + s * 8 + t + 4 * p;
                pa0[s * 2 + p] = __ldg(zfs + a0i + off);
                pa1[s * 2 + p] = __ldg(zfs + a1i + off);
                pb0[s * 2 + p] = __ldg(cbs + b0i + off);
                pb1[s * 2 + p] = __ldg(cbs + b1i + off);
            }
    };
    auto stsAB = [&](int buf) {
        uint32_t* base = bufs + buf * BUF_U32;
        stsA_pk(base, wid, lane, pa0, pa1);
        stsB_pk(base, wid, lane, pb0);
        stsB_pk(base, wid + 8, lane, pb1);
    };

    float acc[4][4][4];
#pragma unroll
    for (int i = 0; i < 4; i++)
#pragma unroll
        for (int j = 0; j < 4; j++)
#pragma unroll
            for (int e = 0; e < 4; e++) acc[i][j][e] = 0.f;

    loadAB(0);
    stsAB(0);
    __syncthreads();

    for (int kk = 0; kk < NCH; kk++) {
        if (kk + 1 < NCH) loadAB(kk + 1);
        compute_chunk(bufs + (kk & 1) * BUF_U32, wm, wn, lane, acc);
        if (kk + 1 < NCH) stsAB((kk + 1) & 1);
        __syncthreads();
    }

    // argmin epilogue: d = cbnorm - 2 * acc / 65536
    const float ds2 = 2.f / 65536.f;
#pragma unroll
    for (int i = 0; i < 4; i++) {
        int rlo = (wm * 4 + i) * 16 + g;
        float bestl = __int_as_float(0x7f800000); int bcl = 0;
        float besth = __int_as_float(0x7f800000); int bch = 0;
#pragma unroll
        for (int j = 0; j < 4; j++) {
            int c = (wn * 4 + j) * 8 + 2 * t;
            float n0 = aux[c], n1 = aux[c + 1];
            float d0 = n0 - ds2 * acc[i][j][0];
            float d1 = n1 - ds2 * acc[i][j][1];
            float d2 = n0 - ds2 * acc[i][j][2];
            float d3 = n1 - ds2 * acc[i][j][3];
            if (d0 < bestl) { bestl = d0; bcl = c; }
            if (d1 < bestl) { bestl = d1; bcl = c + 1; }
            if (d2 < besth) { besth = d2; bch = c; }
            if (d3 < besth) { besth = d3; bch = c + 1; }
        }
        unsigned ul = __float_as_uint(bestl);
        ul ^= (ul & 0x80000000u) ? 0xFFFFFFFFu : 0x80000000u;
        unsigned uh = __float_as_uint(besth);
        uh ^= (uh & 0x80000000u) ? 0xFFFFFFFFu : 0x80000000u;
        atomicMin(&smin[rlo], ((unsigned long long)ul << 32) | (unsigned)(colBase + bcl));
        atomicMin(&smin[rlo + 8], ((unsigned long long)uh << 32) | (unsigned)(colBase + bch));
    }
    __syncthreads();
    if (tid < 128) atomicMin(&g_min[rowBase + tid], smin[tid]);
}

// ===========================================================================
// cbnorm: warp per code row; norms + g_min init + split codebook write
// ===========================================================================
__global__ void cbnorm_kernel(const float* __restrict__ cb) {
    int w = (blockIdx.x * 256 + threadIdx.x) >> 5;   // 8192 warps
    int lane = threadIdx.x & 31;
    const float4* p = reinterpret_cast<const float4*>(cb + (size_t)w * 256);
    float4 v0 = __ldg(p + lane);
    float4 v1 = __ldg(p + lane + 32);
    float s = v0.x * v0.x + v0.y * v0.y + v0.z * v0.z + v0.w * v0.w
            + v1.x * v1.x + v1.y * v1.y + v1.z * v1.z + v1.w * v1.w;
    size_t base = (size_t)w * 128;
    g_cbs[base + 2 * lane + 0] = splitpk(v0.x, v0.y);
    g_cbs[base + 2 * lane + 1] = splitpk(v0.z, v0.w);
    g_cbs[base + 64 + 2 * lane + 0] = splitpk(v1.x, v1.y);
    g_cbs[base + 64 + 2 * lane + 1] = splitpk(v1.z, v1.w);
#pragma unroll
    for (int o = 16; o > 0; o >>= 1) s += __shfl_xor_sync(0xFFFFFFFFu, s, o);
    if (lane == 0) { g_cbnorm[w] = s; g_min[w] = ~0ULL; }
}

// ===========================================================================
// Gather z_q: smem-tiled transpose, coalesced reads AND writes.
// ===========================================================================
__global__ __launch_bounds__(256) void gather_zq(const float* __restrict__ cb,
                                                 float* __restrict__ out) {
    __shared__ float tile[64][65];
    int n = blockIdx.y;
    int cb0 = blockIdx.x * 64;
    int tid = threadIdx.x;

    for (int pb = 0; pb < 256; pb += 64) {
        __syncthreads();
#pragma unroll 4
        for (int it = 0; it < 16; it++) {
            int pl = it * 4 + (tid >> 6);
            int c = tid & 63;
            unsigned id = (unsigned)(g_min[n * 256 + pb + pl] & 0xFFFFFFFFu);
            tile[pl][c] = __ldg(cb + (size_t)id * 256 + cb0 + c);
        }
        __syncthreads();
#pragma unroll 4
        for (int it = 0; it < 16; it++) {
            int c = it * 4 + (tid >> 6);
            int pl = tid & 63;
            out[(size_t)n * 65536 + (size_t)(cb0 + c) * 256 + pb + pl] = tile[pl][c];
        }
    }
}

__global__ void gather_idx(float* __restrict__ out, long idx_off) {
    int row = blockIdx.x * 256 + threadIdx.x;
    unsigned idx = (unsigned)(g_min[row] & 0xFFFFFFFFu);
    out[idx_off + row] = (float)idx;
}

// ===========================================================================
// Launch: prepasses forked onto a second stream, overlapping conv1.
// ===========================================================================
extern "C" void kernel_launch(void* const* d_in, const int* in_sizes, int n_in,
                              void* d_out, int out_size) {
    const float* x  = (const float*)d_in[0];
    const float* w1 = (const float*)d_in[1];
    const float* b1 = (const float*)d_in[2];
    const float* w2 = (const float*)d_in[3];
    const float* b2 = (const float*)d_in[4];
    const float* w3 = (const float*)d_in[5];
    const float* b3 = (const float*)d_in[6];
    const float* w4 = (const float*)d_in[7];
    const float* b4 = (const float*)d_in[8];
    const float* cb = (const float*)d_in[9];
    float* out = (float*)d_out;

    uint2* a1s;  cudaGetSymbolAddress((void**)&a1s,  g_a1s);
    uint2* a2s;  cudaGetSymbolAddress((void**)&a2s,  g_a2s);
    uint2* a3s;  cudaGetSymbolAddress((void**)&a3s,  g_a3s);
    uint2* zfs;  cudaGetSymbolAddress((void**)&zfs,  g_zfs);
    uint2* wt1s; cudaGetSymbolAddress((void**)&wt1s, g_wt1s);
    uint2* wt2s; cudaGetSymbolAddress((void**)&wt2s, g_wt2s);
    uint2* wt3s; cudaGetSymbolAddress((void**)&wt3s, g_wt3s);
    uint2* wt4s; cudaGetSymbolAddress((void**)&wt4s, g_wt4s);
    uint2* cbs;  cudaGetSymbolAddress((void**)&cbs,  g_cbs);

    static int attr_done = 0;
    static cudaStream_t s2 = nullptr;
    static cudaEvent_t evFork = nullptr, evJoin = nullptr;
    if (!attr_done) {
        cudaFuncSetAttribute(conv_mma<64, 128, 128, 128>, cudaFuncAttributeMaxDynamicSharedMemorySize, GEMM_SMEM);
        cudaFuncSetAttribute(conv_mma<128, 256, 64, 64>, cudaFuncAttributeMaxDynamicSharedMemorySize, GEMM_SMEM);
        cudaFuncSetAttribute(conv_mma<256, 256, 32, 32>, cudaFuncAttributeMaxDynamicSharedMemorySize, GEMM_SMEM);
        cudaFuncSetAttribute(vq_mma, cudaFuncAttributeMaxDynamicSharedMemorySize, GEMM_SMEM);
        cudaStreamCreateWithFlags(&s2, cudaStreamNonBlocking);
        cudaEventCreateWithFlags(&evFork, cudaEventDisableTiming);
        cudaEventCreateWithFlags(&evJoin, cudaEventDisableTiming);
        attr_done = 1;
    }

    // conv1's weight split is needed by conv1 itself: run it first on the main
    // stream, then fork the remaining prepasses to overlap conv1.
    wtrans1_kernel<<<6, 256>>>(w1, wt1s);

    cudaEventRecord(evFork, 0);
    cudaStreamWaitEvent(s2, evFork, 0);
    wtrans_kernel<<<(128 * 1024 / 2 + 255) / 256, 256, 0, s2>>>(w2, wt2s, 64, 128);
    wtrans_kernel<<<(256 * 2048 / 2 + 255) / 256, 256, 0, s2>>>(w3, wt3s, 128, 256);
    wtrans_kernel<<<(256 * 4096 / 2 + 255) / 256, 256, 0, s2>>>(w4, wt4s, 256, 256);
    cbnorm_kernel<<<1024, 256, 0, s2>>>(cb);
    cudaEventRecord(evJoin, s2);

    conv1_mma<<<4096, 256>>>(x, wt1s, b1, a1s);
    cudaStreamWaitEvent(0, evJoin, 0);

    // conv chain (split NHWC)
    conv_mma<64, 128, 128, 128><<<dim3(1024, 1), 256, GEMM_SMEM>>>(a1s, wt2s, b2, a2s);
    conv_mma<128, 256, 64, 64><<<dim3(256, 2), 256, GEMM_SMEM>>>(a2s, wt3s, b3, a3s);
    conv_mma<256, 256, 32, 32><<<dim3(64, 2), 256, GEMM_SMEM>>>(a3s, wt4s, b4, zfs);

    // VQ
    vq_mma<<<dim3(64, 64), 256, GEMM_SMEM>>>(zfs, cbs);

    // output: [z_q (2,097,152 floats)] [idx (8,192, cast to float)]
    const long ZQ = 2097152;
    int write_zq = 0, write_idx = 0; long idx_off = 0;
    if (out_size >= (int)(ZQ + 8192)) { write_zq = 1; write_idx = 1; idx_off = ZQ; }
    else if (out_size >= (int)ZQ)     { write_zq = 1; }
    else                              { write_idx = 1; idx_off = 0; }

    if (write_zq) gather_zq<<<dim3(4, 32), 256>>>(cb, out);
    if (write_idx) gather_idx<<<32, 256>>>(out, idx_off);
}

// round 16
// speedup vs baseline: 1.0084x; 1.0084x over previous
#include <cuda_runtime.h>
#include <cuda_fp16.h>
#include <cstdint>

// ===========================================================================
// Scratch (__device__ globals; no allocation allowed)
// Split format: uint2 { hi_half2, lo_half2 } covering 2 consecutive channels,
// value v stored as hi+lo = 256*v (fp16 pair), consumed by fp16x2 MMA scheme.
// ===========================================================================
__device__ uint2 g_a1s[32u * 128u * 128u * 64u / 2];   // conv1 out split NHWC
__device__ uint2 g_a2s[32u * 64u * 64u * 128u / 2];
__device__ uint2 g_a3s[32u * 32u * 32u * 256u / 2];
__device__ uint2 g_zfs[8192u * 256u / 2];              // conv4 out split == zf
__device__ uint2 g_wt1s[64u * 48u / 2];                // w1 split [co][ci*16+tap]
__device__ uint2 g_wt2s[128u * 1024u / 2];             // weights split [co][tap*CI+ci]
__device__ uint2 g_wt3s[256u * 2048u / 2];
__device__ uint2 g_wt4s[256u * 4096u / 2];
__device__ uint2 g_cbs[8192u * 256u / 2];              // codebook split
__device__ float g_cbnorm[8192];
__device__ unsigned long long g_min[8192];

// ===========================================================================
// Split helpers (epilogue/pre-pass only; GEMM mainloops have zero ALU)
// ===========================================================================
__device__ __forceinline__ uint32_t packh2(__half x, __half y) {
    __half2 h = __halves2half2(x, y);
    return *reinterpret_cast<uint32_t*>(&h);
}
__device__ __forceinline__ uint2 splitpk(float x, float y) {
    float sx = x * 256.f, sy = y * 256.f;
    __half hx = __float2half_rn(sx), hy = __float2half_rn(sy);
    float rx = sx - __half2float(hx), ry = sy - __half2float(hy);
    uint2 r;
    r.x = packh2(hx, hy);
    r.y = packh2(__float2half_rn(rx), __float2half_rn(ry));
    return r;
}

__device__ __forceinline__ void mma16(float* d, const uint32_t* a, const uint32_t* b) {
    asm volatile(
        "mma.sync.aligned.m16n8k16.row.col.f32.f16.f16.f32 "
        "{%0,%1,%2,%3}, {%4,%5,%6,%7}, {%8,%9}, {%0,%1,%2,%3};"
        : "+f"(d[0]), "+f"(d[1]), "+f"(d[2]), "+f"(d[3])
        : "r"(a[0]), "r"(a[1]), "r"(a[2]), "r"(a[3]), "r"(b[0]), "r"(b[1]));
}

// SMEM buffer (u32 units): AH[2048] AL[2048] BH[2048] BL[2048] = 8192 u32 = 32KB.
static constexpr int BUF_U32 = 8192;
static constexpr int GEMM_SMEM = 128 * 4 + 2 * BUF_U32 * 4;   // 66048 bytes

// Compute one K=32 chunk. Warp tile 64x32 (4 m-blocks x 4 n-blocks), 8 warps 2x4.
__device__ __forceinline__ void compute_chunk(const uint32_t* buf, int wm, int wn, int lane,
                                              float acc[4][4][4]) {
    const uint32_t* AH = buf;
    const uint32_t* AL = buf + 2048;
    const uint32_t* BH = buf + 4096;
    const uint32_t* BL = buf + 6144;
#pragma unroll
    for (int s = 0; s < 2; s++) {
        uint4 ah[4], al[4];
        uint2 bh[4], bl[4];
#pragma unroll
        for (int i = 0; i < 4; i++) {
            int idx = ((s * 8 + wm * 4 + i) * 32 + lane) * 4;
            ah[i] = *reinterpret_cast<const uint4*>(AH + idx);
            al[i] = *reinterpret_cast<const uint4*>(AL + idx);
        }
#pragma unroll
        for (int j = 0; j < 4; j++) {
            int idx = ((s * 16 + wn * 4 + j) * 32 + lane) * 2;
            bh[j] = *reinterpret_cast<const uint2*>(BH + idx);
            bl[j] = *reinterpret_cast<const uint2*>(BL + idx);
        }
#pragma unroll
        for (int i = 0; i < 4; i++)
#pragma unroll
            for (int j = 0; j < 4; j++) {
                mma16(acc[i][j], &ah[i].x, &bh[j].x);
                mma16(acc[i][j], &al[i].x, &bh[j].x);
                mma16(acc[i][j], &ah[i].x, &bl[j].x);
            }
    }
}

// Fill stores: pa0/pa1 = rows g,g+8, [s*2+p] uint2 pairs; pure register packing.
__device__ __forceinline__ void stsA_pk(uint32_t* base, int mblk, int lane,
                                        const uint2* pa0, const uint2* pa1) {
#pragma unroll
    for (int s = 0; s < 2; s++) {
        uint4 h = make_uint4(pa0[s * 2 + 0].x, pa1[s * 2 + 0].x, pa0[s * 2 + 1].x, pa1[s * 2 + 1].x);
        uint4 l = make_uint4(pa0[s * 2 + 0].y, pa1[s * 2 + 0].y, pa0[s * 2 + 1].y, pa1[s * 2 + 1].y);
        int idx = ((s * 8 + mblk) * 32 + lane) * 4;
        *reinterpret_cast<uint4*>(base + idx) = h;
        *reinterpret_cast<uint4*>(base + 2048 + idx) = l;
    }
}
__device__ __forceinline__ void stsB_pk(uint32_t* base, int nblk, int lane, const uint2* pb) {
#pragma unroll
    for (int s = 0; s < 2; s++) {
        uint2 h = make_uint2(pb[s * 2 + 0].x, pb[s * 2 + 1].x);
        uint2 l = make_uint2(pb[s * 2 + 0].y, pb[s * 2 + 1].y);
        int idx = ((s * 16 + nblk) * 32 + lane) * 2;
        *reinterpret_cast<uint2*>(base + 4096 + idx) = h;
        *reinterpret_cast<uint2*>(base + 6144 + idx) = l;
    }
}

// ===========================================================================
// Fused prep kernel: all weight splits + codebook norms/split + g_min init.
// Block ranges: [0,2048) wt4 | [2048,3072) wt3 | [3072,3328) wt2
//               [3328,3334) wt1 | [3334,4358) cbnorm
// ===========================================================================
__device__ __forceinline__ void wtrans_part(const float* __restrict__ w,
                                            uint2* __restrict__ wTs, int CI, int id) {
    int K = CI * 16;
    int co = id / (K / 2);
    int r2 = id % (K / 2);
    int k0 = 2 * r2, k1 = k0 + 1;
    int tap0 = k0 / CI, ci0 = k0 % CI;
    int tap1 = k1 / CI, ci1 = k1 % CI;
    wTs[id] = splitpk(w[(co * CI + ci0) * 16 + tap0], w[(co * CI + ci1) * 16 + tap1]);
}

__global__ __launch_bounds__(256) void prep_kernel(
    const float* __restrict__ w1, const float* __restrict__ w2,
    const float* __restrict__ w3, const float* __restrict__ w4,
    const float* __restrict__ cb,
    uint2* __restrict__ wt1s, uint2* __restrict__ wt2s,
    uint2* __restrict__ wt3s, uint2* __restrict__ wt4s) {
    int bid = blockIdx.x;
    int tid = threadIdx.x;
    if (bid < 2048) {
        wtrans_part(w4, wt4s, 256, bid * 256 + tid);
    } else if (bid < 3072) {
        wtrans_part(w3, wt3s, 128, (bid - 2048) * 256 + tid);
    } else if (bid < 3328) {
        wtrans_part(w2, wt2s, 64, (bid - 3072) * 256 + tid);
    } else if (bid < 3334) {
        int id = (bid - 3328) * 256 + tid;      // 0..1535
        int co = id / 24;
        int k0 = 2 * (id % 24);
        g_wt1s[id] = splitpk(w1[co * 48 + k0], w1[co * 48 + k0 + 1]);
    } else {
        // cbnorm: warp per code row
        int w = ((bid - 3334) * 256 + tid) >> 5;   // 0..8191
        int lane = tid & 31;
        const float4* p = reinterpret_cast<const float4*>(cb + (size_t)w * 256);
        float4 v0 = __ldg(p + lane);
        float4 v1 = __ldg(p + lane + 32);
        float s = v0.x * v0.x + v0.y * v0.y + v0.z * v0.z + v0.w * v0.w
                + v1.x * v1.x + v1.y * v1.y + v1.z * v1.z + v1.w * v1.w;
        size_t base = (size_t)w * 128;
        g_cbs[base + 2 * lane + 0] = splitpk(v0.x, v0.y);
        g_cbs[base + 2 * lane + 1] = splitpk(v0.z, v0.w);
        g_cbs[base + 64 + 2 * lane + 0] = splitpk(v1.x, v1.y);
        g_cbs[base + 64 + 2 * lane + 1] = splitpk(v1.z, v1.w);
#pragma unroll
        for (int o = 16; o > 0; o >>= 1) s += __shfl_xor_sync(0xFFFFFFFFu, s, o);
        if (lane == 0) { g_cbnorm[w] = s; g_min[w] = ~0ULL; }
    }
}

// ===========================================================================
// Conv1 tensorized: M=128 pixels x N=64 cout, K=48 (s=ci). NCHW in -> split NHWC.
// One-shot K (3 k16-steps), 8 warps 4m x 2n, warp tile 32x32.
// ===========================================================================
__global__ __launch_bounds__(256) void conv1_mma(const float* __restrict__ x,
                                                 const uint2* __restrict__ wt1s,
                                                 const float* __restrict__ bias,
                                                 uint2* __restrict__ outs) {
    __shared__ float aux[64];
    __shared__ __align__(16) uint32_t sbuf[9216];   // AH 3072 | AL 3072 | BH 1536 | BL 1536
    uint32_t* AH = sbuf;
    uint32_t* AL = sbuf + 3072;
    uint32_t* BH = sbuf + 6144;
    uint32_t* BL = sbuf + 7680;

    int tid = threadIdx.x, lane = tid & 31, wid = tid >> 5;
    int g = lane >> 2, t = lane & 3;
    int rowBase = blockIdx.x * 128;
    if (tid < 64) aux[tid] = bias[tid];

    // --- A fill: warp wid = m-block; rows r0=base+wid*16+g, r1=r0+8 ---
    int r0 = rowBase + wid * 16 + g;
    int r1 = r0 + 8;
    int n0 = r0 >> 14, rp0 = r0 & 16383;
    int n1 = r1 >> 14, rp1 = r1 & 16383;
    int hb0 = 2 * (rp0 >> 7) - 1, wb0 = 2 * (rp0 & 127) - 1;
    int hb1 = 2 * (rp1 >> 7) - 1, wb1 = 2 * (rp1 & 127) - 1;

    uint2 pa0[6], pa1[6];   // [ci*2 + p], pair of taps (2t+8p, 2t+8p+1)
#pragma unroll
    for (int ci = 0; ci < 3; ci++) {
        const float* xc0 = x + (((size_t)n0 * 3 + ci) << 16);
        const float* xc1 = x + (((size_t)n1 * 3 + ci) << 16);
#pragma unroll
        for (int p = 0; p < 2; p++) {
            int tapA = 2 * t + 8 * p;
            int tapB = tapA + 1;
            int khA = tapA >> 2, kwA = tapA & 3;
            int khB = tapB >> 2, kwB = tapB & 3;
            int hA0 = hb0 + khA, wA0 = wb0 + kwA, hB0 = hb0 + khB, wB0 = wb0 + kwB;
            int hA1 = hb1 + khA, wA1 = wb1 + kwA, hB1 = hb1 + khB, wB1 = wb1 + kwB;
            float vA0 = ((unsigned)hA0 < 256u && (unsigned)wA0 < 256u) ? __ldg(xc0 + hA0 * 256 + wA0) : 0.f;
            float vB0 = ((unsigned)hB0 < 256u && (unsigned)wB0 < 256u) ? __ldg(xc0 + hB0 * 256 + wB0) : 0.f;
            float vA1 = ((unsigned)hA1 < 256u && (unsigned)wA1 < 256u) ? __ldg(xc1 + hA1 * 256 + wA1) : 0.f;
            float vB1 = ((unsigned)hB1 < 256u && (unsigned)wB1 < 256u) ? __ldg(xc1 + hB1 * 256 + wB1) : 0.f;
            pa0[ci * 2 + p] = splitpk(vA0, vB0);
            pa1[ci * 2 + p] = splitpk(vA1, vB1);
        }
    }
#pragma unroll
    for (int s = 0; s < 3; s++) {
        uint4 h = make_uint4(pa0[s * 2 + 0].x, pa1[s * 2 + 0].x, pa0[s * 2 + 1].x, pa1[s * 2 + 1].x);
        uint4 l = make_uint4(pa0[s * 2 + 0].y, pa1[s * 2 + 0].y, pa0[s * 2 + 1].y, pa1[s * 2 + 1].y);
        int idx = ((s * 8 + wid) * 32 + lane) * 4;
        *reinterpret_cast<uint4*>(AH + idx) = h;
        *reinterpret_cast<uint4*>(AL + idx) = l;
    }

    // --- B fill: warp wid = n-block; col = wid*8 + g; 24 uint2 per co row ---
    {
        size_t wr = (size_t)(wid * 8 + g) * 24;
#pragma unroll
        for (int s = 0; s < 3; s++) {
            uint2 u0 = __ldg(wt1s + wr + s * 8 + t);        // k = s*16 + 2t
            uint2 u1 = __ldg(wt1s + wr + s * 8 + t + 4);    // k = s*16 + 2t + 8
            int idx = ((s * 8 + wid) * 32 + lane) * 2;
            *reinterpret_cast<uint2*>(BH + idx) = make_uint2(u0.x, u1.x);
            *reinterpret_cast<uint2*>(BL + idx) = make_uint2(u0.y, u1.y);
        }
    }
    __syncthreads();

    // --- compute: warp 4m x 2n; warp tile 32 rows (2 mblk) x 32 cols (4 nblk) ---
    int wm = wid >> 1, wn = wid & 1;
    float acc[2][4][4];
#pragma unroll
    for (int i = 0; i < 2; i++)
#pragma unroll
        for (int j = 0; j < 4; j++)
#pragma unroll
            for (int e = 0; e < 4; e++) acc[i][j][e] = 0.f;

#pragma unroll
    for (int s = 0; s < 3; s++) {
        uint4 ah[2], al[2];
        uint2 bh[4], bl[4];
#pragma unroll
        for (int i = 0; i < 2; i++) {
            int idx = ((s * 8 + wm * 2 + i) * 32 + lane) * 4;
            ah[i] = *reinterpret_cast<const uint4*>(AH + idx);
            al[i] = *reinterpret_cast<const uint4*>(AL + idx);
        }
#pragma unroll
        for (int j = 0; j < 4; j++) {
            int idx = ((s * 8 + wn * 4 + j) * 32 + lane) * 2;
            bh[j] = *reinterpret_cast<const uint2*>(BH + idx);
            bl[j] = *reinterpret_cast<const uint2*>(BL + idx);
        }
#pragma unroll
        for (int i = 0; i < 2; i++)
#pragma unroll
            for (int j = 0; j < 4; j++) {
                mma16(acc[i][j], &ah[i].x, &bh[j].x);
                mma16(acc[i][j], &al[i].x, &bh[j].x);
                mma16(acc[i][j], &ah[i].x, &bl[j].x);
            }
    }

    // --- epilogue: descale + bias + relu, split NHWC store ---
    const float ds = 1.f / 65536.f;
#pragma unroll
    for (int i = 0; i < 2; i++) {
        int rlo = rowBase + (wm * 2 + i) * 16 + g;
        int rhi = rlo + 8;
#pragma unroll
        for (int j = 0; j < 4; j++) {
            int c = (wn * 4 + j) * 8 + 2 * t;
            float b0 = aux[c], b1 = aux[c + 1];
            outs[((size_t)rlo * 64 + c) >> 1] =
                splitpk(fmaxf(acc[i][j][0] * ds + b0, 0.f), fmaxf(acc[i][j][1] * ds + b1, 0.f));
            outs[((size_t)rhi * 64 + c) >> 1] =
                splitpk(fmaxf(acc[i][j][2] * ds + b0, 0.f), fmaxf(acc[i][j][3] * ds + b1, 0.f));
        }
    }
}

// ===========================================================================
// Tensor-core implicit-GEMM conv (k=4 s=2 p=1) + bias + ReLU.
// split NHWC in -> split NHWC out. Block 128x128, K=CI*16 by 32; 8 warps 64x32.
// Mainloop: LDG(uint2) -> STS -> LDS -> MMA. No ALU.
// ===========================================================================
template <int CI, int CO, int HI, int WI>
__global__ __launch_bounds__(256) void conv_mma(const uint2* __restrict__ in,
                                                const uint2* __restrict__ wTs,
                                                const float* __restrict__ bias,
                                                uint2* __restrict__ outs) {
    constexpr int HO = HI / 2, WO = WI / 2;
    constexpr int K = CI * 16;
    constexpr int NCH = K / 32;
    extern __shared__ __align__(16) float smem[];
    float* aux = smem;
    uint32_t* bufs = reinterpret_cast<uint32_t*>(smem + 128);

    int tid = threadIdx.x, lane = tid & 31, wid = tid >> 5;
    int wm = wid >> 2, wn = wid & 3;
    int g = lane >> 2, t = lane & 3;
    int rowBase = blockIdx.x * 128;
    int co0 = blockIdx.y * 128;

    if (tid < 128) aux[tid] = bias[co0 + tid];

    // --- A fill: warp wid = m-block; rows g and g+8 ---
    int rA0 = rowBase + wid * 16 + g;
    int rA1 = rA0 + 8;
    int n0 = rA0 / (HO * WO), rp0 = rA0 % (HO * WO);
    int n1 = rA1 / (HO * WO), rp1 = rA1 % (HO * WO);
    int hb0 = 2 * (rp0 / WO) - 1, wb0 = 2 * (rp0 % WO) - 1;
    int hb1 = 2 * (rp1 / WO) - 1, wb1 = 2 * (rp1 % WO) - 1;
    size_t ab0 = (size_t)n0 * HI * WI * CI;
    size_t ab1 = (size_t)n1 * HI * WI * CI;

    // --- B fill: warp wid covers n-blocks wid, wid+8; col = nblk*8 + g ---
    size_t wb0i = ((size_t)(co0 + wid * 8 + g) * K) >> 1;
    size_t wb1i = ((size_t)(co0 + (wid + 8) * 8 + g) * K) >> 1;

    uint2 pa0[4], pa1[4], pb0[4], pb1[4];
    auto loadA = [&](int kk) {
        int kk32 = kk * 32;
        int tap = kk32 / CI, ci0 = kk32 % CI;
        int kh = tap >> 2, kw = tap & 3;
        int hi0 = hb0 + kh, wi0 = wb0 + kw;
        int hi1 = hb1 + kh, wi1 = wb1 + kw;
        bool ok0 = (unsigned)hi0 < (unsigned)HI && (unsigned)wi0 < (unsigned)WI;
        bool ok1 = (unsigned)hi1 < (unsigned)HI && (unsigned)wi1 < (unsigned)WI;
        size_t b0 = (ab0 + ((size_t)hi0 * WI + wi0) * CI + ci0) >> 1;
        size_t b1 = (ab1 + ((size_t)hi1 * WI + wi1) * CI + ci0) >> 1;
        uint2 z = make_uint2(0u, 0u);
#pragma unroll
        for (int s = 0; s < 2; s++)
#pragma unroll
            for (int p = 0; p < 2; p++) {
                int off = s * 8 + t + 4 * p;
                pa0[s * 2 + p] = ok0 ? __ldg(in + b0 + off) : z;
                pa1[s * 2 + p] = ok1 ? __ldg(in + b1 + off) : z;
            }
    };
    auto loadB = [&](int kk) {
#pragma unroll
        for (int s = 0; s < 2; s++)
#pragma unroll
            for (int p = 0; p < 2; p++) {
                int off = kk * 16 + s * 8 + t + 4 * p;
                pb0[s * 2 + p] = __ldg(wTs + wb0i + off);
                pb1[s * 2 + p] = __ldg(wTs + wb1i + off);
            }
    };
    auto stsAB = [&](int buf) {
        uint32_t* base = bufs + buf * BUF_U32;
        stsA_pk(base, wid, lane, pa0, pa1);
        stsB_pk(base, wid, lane, pb0);
        stsB_pk(base, wid + 8, lane, pb1);
    };

    float acc[4][4][4];
#pragma unroll
    for (int i = 0; i < 4; i++)
#pragma unroll
        for (int j = 0; j < 4; j++)
#pragma unroll
            for (int e = 0; e < 4; e++) acc[i][j][e] = 0.f;

    loadA(0); loadB(0);
    stsAB(0);
    __syncthreads();

    for (int kk = 0; kk < NCH; kk++) {
        if (kk + 1 < NCH) { loadA(kk + 1); loadB(kk + 1); }
        compute_chunk(bufs + (kk & 1) * BUF_U32, wm, wn, lane, acc);
        if (kk + 1 < NCH) stsAB((kk + 1) & 1);
        __syncthreads();
    }

    // epilogue: descale + bias + relu, split store
    const float ds = 1.f / 65536.f;
#pragma unroll
    for (int i = 0; i < 4; i++) {
        int rlo = rowBase + (wm * 4 + i) * 16 + g;
        int rhi = rlo + 8;
#pragma unroll
        for (int j = 0; j < 4; j++) {
            int c = (wn * 4 + j) * 8 + 2 * t;
            float b0 = aux[c], b1 = aux[c + 1];
            outs[((size_t)rlo * CO + co0 + c) >> 1] =
                splitpk(fmaxf(acc[i][j][0] * ds + b0, 0.f), fmaxf(acc[i][j][1] * ds + b1, 0.f));
            outs[((size_t)rhi * CO + co0 + c) >> 1] =
                splitpk(fmaxf(acc[i][j][2] * ds + b0, 0.f), fmaxf(acc[i][j][3] * ds + b1, 0.f));
        }
    }
}

// ===========================================================================
// Tensor-core VQ: S = zf @ cb^T; d = ||c||^2 - 2S; row argmin. Split inputs.
// ===========================================================================
__global__ __launch_bounds__(256) void vq_mma(const uint2* __restrict__ zfs,
                                              const uint2* __restrict__ cbs) {
    constexpr int NCH = 8;   // K = 256
    extern __shared__ __align__(16) float smem[];
    float* aux = smem;
    uint32_t* bufs = reinterpret_cast<uint32_t*>(smem + 128);
    __shared__ unsigned long long smin[128];

    int tid = threadIdx.x, lane = tid & 31, wid = tid >> 5;
    int wm = wid >> 2, wn = wid & 3;
    int g = lane >> 2, t = lane & 3;
    int colBase = blockIdx.x * 128;
    int rowBase = blockIdx.y * 128;

    if (tid < 128) { aux[tid] = g_cbnorm[colBase + tid]; smin[tid] = ~0ULL; }

    size_t a0i = ((size_t)(rowBase + wid * 16 + g) * 256) >> 1;
    size_t a1i = a0i + 1024;    // +8 rows
    size_t b0i = ((size_t)(colBase + wid * 8 + g) * 256) >> 1;
    size_t b1i = ((size_t)(colBase + (wid + 8) * 8 + g) * 256) >> 1;

    uint2 pa0[4], pa1[4], pb0[4], pb1[4];
    auto loadAB = [&](int kk) {
#pragma unroll
        for (int s = 0; s < 2; s++)
#pragma unroll
            for (int p = 0; p < 2; p++) {
                int off = kk * 16 + s * 8 + t + 4 * p;
                pa0[s * 2 + p] = __ldg(zfs + a0i + off);
                pa1[s * 2 + p] = __ldg(zfs + a1i + off);
                pb0[s * 2 + p] = __ldg(cbs + b0i + off);
                pb1[s * 2 + p] = __ldg(cbs + b1i + off);
            }
    };
    auto stsAB = [&](int buf) {
        uint32_t* base = bufs + buf * BUF_U32;
        stsA_pk(base, wid, lane, pa0, pa1);
        stsB_pk(base, wid, lane, pb0);
        stsB_pk(base, wid + 8, lane, pb1);
    };

    float acc[4][4][4];
#pragma unroll
    for (int i = 0; i < 4; i++)
#pragma unroll
        for (int j = 0; j < 4; j++)
#pragma unroll
            for (int e = 0; e < 4; e++) acc[i][j][e] = 0.f;

    loadAB(0);
    stsAB(0);
    __syncthreads();

    for (int kk = 0; kk < NCH; kk++) {
        if (kk + 1 < NCH) loadAB(kk + 1);
        compute_chunk(bufs + (kk & 1) * BUF_U32, wm, wn, lane, acc);
        if (kk + 1 < NCH) stsAB((kk + 1) & 1);
        __syncthreads();
    }

    // argmin epilogue: d = cbnorm - 2 * acc / 65536
    const float ds2 = 2.f / 65536.f;
#pragma unroll
    for (int i = 0; i < 4; i++) {
        int rlo = (wm * 4 + i) * 16 + g;
        float bestl = __int_as_float(0x7f800000); int bcl = 0;
        float besth = __int_as_float(0x7f800000); int bch = 0;
#pragma unroll
        for (int j = 0; j < 4; j++) {
            int c = (wn * 4 + j) * 8 + 2 * t;
            float n0 = aux[c], n1 = aux[c + 1];
            float d0 = n0 - ds2 * acc[i][j][0];
            float d1 = n1 - ds2 * acc[i][j][1];
            float d2 = n0 - ds2 * acc[i][j][2];
            float d3 = n1 - ds2 * acc[i][j][3];
            if (d0 < bestl) { bestl = d0; bcl = c; }
            if (d1 < bestl) { bestl = d1; bcl = c + 1; }
            if (d2 < besth) { besth = d2; bch = c; }
            if (d3 < besth) { besth = d3; bch = c + 1; }
        }
        unsigned ul = __float_as_uint(bestl);
        ul ^= (ul & 0x80000000u) ? 0xFFFFFFFFu : 0x80000000u;
        unsigned uh = __float_as_uint(besth);
        uh ^= (uh & 0x80000000u) ? 0xFFFFFFFFu : 0x80000000u;
        atomicMin(&smin[rlo], ((unsigned long long)ul << 32) | (unsigned)(colBase + bcl));
        atomicMin(&smin[rlo + 8], ((unsigned long long)uh << 32) | (unsigned)(colBase + bch));
    }
    __syncthreads();
    if (tid < 128) atomicMin(&g_min[rowBase + tid], smin[tid]);
}

// ===========================================================================
// Gather z_q (+ optional idx fold-in): smem-tiled transpose, coalesced I/O.
// ===========================================================================
__global__ __launch_bounds__(256) void gather_zq(const float* __restrict__ cb,
                                                 float* __restrict__ out,
                                                 int write_idx, long idx_off) {
    __shared__ float tile[64][65];
    int n = blockIdx.y;
    int cb0 = blockIdx.x * 64;
    int tid = threadIdx.x;

    if (write_idx && blockIdx.x == 0) {
        unsigned idx = (unsigned)(g_min[n * 256 + tid] & 0xFFFFFFFFu);
        out[idx_off + n * 256 + tid] = (float)idx;
    }

    for (int pb = 0; pb < 256; pb += 64) {
        __syncthreads();
#pragma unroll 4
        for (int it = 0; it < 16; it++) {
            int pl = it * 4 + (tid >> 6);
            int c = tid & 63;
            unsigned id = (unsigned)(g_min[n * 256 + pb + pl] & 0xFFFFFFFFu);
            tile[pl][c] = __ldg(cb + (size_t)id * 256 + cb0 + c);
        }
        __syncthreads();
#pragma unroll 4
        for (int it = 0; it < 16; it++) {
            int c = it * 4 + (tid >> 6);
            int pl = tid & 63;
            out[(size_t)n * 65536 + (size_t)(cb0 + c) * 256 + pb + pl] = tile[pl][c];
        }
    }
}

__global__ void gather_idx(float* __restrict__ out, long idx_off) {
    int row = blockIdx.x * 256 + threadIdx.x;
    unsigned idx = (unsigned)(g_min[row] & 0xFFFFFFFFu);
    out[idx_off + row] = (float)idx;
}

// ===========================================================================
// Launch (serial, proven ordering; fused prep)
// ===========================================================================
extern "C" void kernel_launch(void* const* d_in, const int* in_sizes, int n_in,
                              void* d_out, int out_size) {
    const float* x  = (const float*)d_in[0];
    const float* w1 = (const float*)d_in[1];
    const float* b1 = (const float*)d_in[2];
    const float* w2 = (const float*)d_in[3];
    const float* b2 = (const float*)d_in[4];
    const float* w3 = (const float*)d_in[5];
    const float* b3 = (const float*)d_in[6];
    const float* w4 = (const float*)d_in[7];
    const float* b4 = (const float*)d_in[8];
    const float* cb = (const float*)d_in[9];
    float* out = (float*)d_out;

    uint2* a1s;  cudaGetSymbolAddress((void**)&a1s,  g_a1s);
    uint2* a2s;  cudaGetSymbolAddress((void**)&a2s,  g_a2s);
    uint2* a3s;  cudaGetSymbolAddress((void**)&a3s,  g_a3s);
    uint2* zfs;  cudaGetSymbolAddress((void**)&zfs,  g_zfs);
    uint2* wt1s; cudaGetSymbolAddress((void**)&wt1s, g_wt1s);
    uint2* wt2s; cudaGetSymbolAddress((void**)&wt2s, g_wt2s);
    uint2* wt3s; cudaGetSymbolAddress((void**)&wt3s, g_wt3s);
    uint2* wt4s; cudaGetSymbolAddress((void**)&wt4s, g_wt4s);
    uint2* cbs;  cudaGetSymbolAddress((void**)&cbs,  g_cbs);

    static int attr_done = 0;
    if (!attr_done) {
        cudaFuncSetAttribute(conv_mma<64, 128, 128, 128>, cudaFuncAttributeMaxDynamicSharedMemorySize, GEMM_SMEM);
        cudaFuncSetAttribute(conv_mma<128, 256, 64, 64>, cudaFuncAttributeMaxDynamicSharedMemorySize, GEMM_SMEM);
        cudaFuncSetAttribute(conv_mma<256, 256, 32, 32>, cudaFuncAttributeMaxDynamicSharedMemorySize, GEMM_SMEM);
        cudaFuncSetAttribute(vq_mma, cudaFuncAttributeMaxDynamicSharedMemorySize, GEMM_SMEM);
        attr_done = 1;
    }

    // fused prep: all weight splits + codebook norms/split + g_min init
    prep_kernel<<<4358, 256>>>(w1, w2, w3, w4, cb, wt1s, wt2s, wt3s, wt4s);

    // conv chain (split NHWC)
    conv1_mma<<<4096, 256>>>(x, wt1s, b1, a1s);
    conv_mma<64, 128, 128, 128><<<dim3(1024, 1), 256, GEMM_SMEM>>>(a1s, wt2s, b2, a2s);
    conv_mma<128, 256, 64, 64><<<dim3(256, 2), 256, GEMM_SMEM>>>(a2s, wt3s, b3, a3s);
    conv_mma<256, 256, 32, 32><<<dim3(64, 2), 256, GEMM_SMEM>>>(a3s, wt4s, b4, zfs);

    // VQ
    vq_mma<<<dim3(64, 64), 256, GEMM_SMEM>>>(zfs, cbs);

    // output: [z_q (2,097,152 floats)] [idx (8,192, cast to float)]
    const long ZQ = 2097152;
    int write_zq = 0, write_idx = 0; long idx_off = 0;
    if (out_size >= (int)(ZQ + 8192)) { write_zq = 1; write_idx = 1; idx_off = ZQ; }
    else if (out_size >= (int)ZQ)     { write_zq = 1; }
    else                              { write_idx = 1; idx_off = 0; }

    if (write_zq) gather_zq<<<dim3(4, 32), 256>>>(cb, out, write_idx, idx_off);
    else if (write_idx) gather_idx<<<32, 256>>>(out, idx_off);
}